// round 14
// baseline (speedup 1.0000x reference)
#include <cuda_runtime.h>
#include <cuda_bf16.h>
#include <cstdint>
#include <cstddef>

// ---------------- Problem dims ----------------
#define D_DIM 2048
#define B_DIM 4096
#define H_LAYERS 3

// ---------------- Device scratch ----------------
__device__ __nv_bfloat16 g_Whi[(size_t)H_LAYERS * D_DIM * D_DIM];
__device__ __nv_bfloat16 g_Wlo[(size_t)H_LAYERS * D_DIM * D_DIM];
__device__ float g_bias[H_LAYERS * D_DIM];
__device__ float g_wo[D_DIM];
__device__ __nv_bfloat16 g_ahi[2][(size_t)B_DIM * D_DIM];
__device__ __nv_bfloat16 g_alo[2][(size_t)B_DIM * D_DIM];

// ---------------- Scheduler state (reset by prologue each launch) ----------------
__device__ int g_ticket;
__device__ int g_band[2][32];     // finished n-tiles per (layer, m-band)
__device__ int g_prep[2];         // finished prep chunks for W1, W2

// ---------------- helpers ----------------
__device__ __forceinline__ uint32_t smem_u32(const void* p) {
    uint32_t a;
    asm("{ .reg .u64 t; cvta.to.shared.u64 t, %1; cvt.u32.u64 %0, t; }" : "=r"(a) : "l"(p));
    return a;
}

#define CP_ASYNC16(dst, src) \
    asm volatile("cp.async.cg.shared.global [%0], [%1], 16;" :: "r"(dst), "l"(src) : "memory")
#define CP_COMMIT() asm volatile("cp.async.commit_group;" ::: "memory")
#define CP_WAIT(n)  asm volatile("cp.async.wait_group %0;" :: "n"(n) : "memory")

#define LDSM4(r0, r1, r2, r3, addr) \
    asm volatile("ldmatrix.sync.aligned.m8n8.x4.shared.b16 {%0,%1,%2,%3}, [%4];" \
                 : "=r"(r0), "=r"(r1), "=r"(r2), "=r"(r3) : "r"(addr))

__device__ __forceinline__ void mma_bf16(float& c0, float& c1, float& c2, float& c3,
                                         uint32_t a0, uint32_t a1, uint32_t a2, uint32_t a3,
                                         uint32_t b0, uint32_t b1) {
    asm volatile(
        "mma.sync.aligned.m16n8k16.row.col.f32.bf16.bf16.f32 "
        "{%0,%1,%2,%3}, {%4,%5,%6,%7}, {%8,%9}, {%0,%1,%2,%3};"
        : "+f"(c0), "+f"(c1), "+f"(c2), "+f"(c3)
        : "r"(a0), "r"(a1), "r"(a2), "r"(a3), "r"(b0), "r"(b1));
}

// MUFU-free e^x (poly 2^r + exponent bit trick)
__device__ __forceinline__ float fast_exp(float x) {
    float y = x * 1.4426950408889634f;
    float f = floorf(y);
    float r = y - f;
    float p = 1.53989903e-4f;
    p = fmaf(p, r, 1.33335581e-3f);
    p = fmaf(p, r, 9.61817249e-3f);
    p = fmaf(p, r, 5.55041087e-2f);
    p = fmaf(p, r, 2.40226507e-1f);
    p = fmaf(p, r, 6.93147181e-1f);
    p = fmaf(p, r, 1.0f);
    int i = (int)f;
    if (i < -126) i = -126;
    return p * __int_as_float((i + 127) << 23);
}

__device__ __forceinline__ float softplus_fast(float x) {
    float t = fast_exp(x);
    if (t < 0.25f) {
        float p = fmaf(t, -0.125f, 0.14285714285714285f);
        p = fmaf(t, p, -0.16666666666666666f);
        p = fmaf(t, p, 0.2f);
        p = fmaf(t, p, -0.25f);
        p = fmaf(t, p, 0.3333333333333333f);
        p = fmaf(t, p, -0.5f);
        p = fmaf(t, p, 1.0f);
        return t * p;
    }
    return 0.6931471805599453f * log2f(1.0f + t);
}

__device__ __forceinline__ void split_bf16(float v, __nv_bfloat16& hi, __nv_bfloat16& lo) {
    hi = __float2bfloat16_rn(v);
    lo = __float2bfloat16_rn(v - __bfloat162float(hi));
}

__device__ __forceinline__ void prep_slab(const float4* __restrict__ mu,
                                          const float4* __restrict__ rho,
                                          const float4* __restrict__ eps,
                                          size_t off, size_t n,
                                          size_t start, size_t stride)
{
    for (size_t i = start; i < n; i += stride) {
        float4 m = mu[off + i], r = rho[off + i], e = eps[off + i];
        float w0 = fmaf(e.x, softplus_fast(r.x), m.x);
        float w1 = fmaf(e.y, softplus_fast(r.y), m.y);
        float w2 = fmaf(e.z, softplus_fast(r.z), m.z);
        float w3 = fmaf(e.w, softplus_fast(r.w), m.w);
        __nv_bfloat16 h[4], l[4];
        split_bf16(w0, h[0], l[0]);
        split_bf16(w1, h[1], l[1]);
        split_bf16(w2, h[2], l[2]);
        split_bf16(w3, h[3], l[3]);
        reinterpret_cast<ulonglong1*>(g_Whi)[off + i].x =
            *reinterpret_cast<unsigned long long*>(h);
        reinterpret_cast<ulonglong1*>(g_Wlo)[off + i].x =
            *reinterpret_cast<unsigned long long*>(l);
    }
}

// ---------------- GEMM config (round-13 proven engine) ----------------
#define BM 128
#define BN 128
#define BK 32
#define NKT (D_DIM / BK)          // 64
#define PLANE_B 8192              // 128 rows * 64B
#define STAGE_B (4 * PLANE_B)     // 32768 B
#define NSTAGE 3
#define SMEM_TOTAL (NSTAGE * STAGE_B)   // 98304 B -> 2 CTAs/SM

// ---- dependency-safe queue: prep BEFORE its consumers, producers >= 576 tickets ahead ----
#define L_TILES 512
#define PREP_CHUNKS 64
#define Q_P1 0
#define Q_L0 (Q_P1 + PREP_CHUNKS)   // 64
#define Q_P2 (Q_L0 + L_TILES)       // 576
#define Q_L1 (Q_P2 + PREP_CHUNKS)   // 640
#define Q_L2 (Q_L1 + L_TILES)       // 1152
#define Q_TOTAL (Q_L2 + L_TILES)    // 1664
#define NPERSIST 304

__global__ void __launch_bounds__(128, 2)
fused_net(const float4* __restrict__ pmu, const float4* __restrict__ prho,
          const float4* __restrict__ peps, float* __restrict__ out)
{
    extern __shared__ __nv_bfloat16 smem[];
    __shared__ int sticket;

    const int tid = threadIdx.x;
    const int wid = tid >> 5, lane = tid & 31;
    const int gid = lane >> 2, tig = lane & 3;

    // loader mapping (tile-invariant)
    const int lrow = tid >> 2;
    const int lc = tid & 3;
    const int pc = lc ^ ((lrow >> 1) & 3);
    const uint32_t sbase = smem_u32(smem);
    const uint32_t dst_off = (uint32_t)(lrow * 64 + pc * 16);

    // warp tiling constants
    const int warp_m = (wid & 1) * 64;
    const int warp_n = (wid >> 1) * 64;
    const int a_row = warp_m + ((lane >> 3) & 1) * 8 + (lane & 7);
    const uint32_t a_base = (uint32_t)(a_row * 64);
    const int a_sw = (a_row >> 1) & 3;
    const int a_half = lane >> 4;
    const int b_row = warp_n + (lane >> 4) * 8 + (lane & 7);
    const uint32_t b_base = (uint32_t)(b_row * 64);
    const int b_sw = (b_row >> 1) & 3;
    const int b_half = (lane >> 3) & 1;

    while (true) {
        if (tid == 0) sticket = atomicAdd(&g_ticket, 1);
        __syncthreads();
        const int t = sticket;
        __syncthreads();
        if (t >= Q_TOTAL) return;

        // ---------- prep chunks (placed BEFORE their consumer layers) ----------
        if (t < Q_L0 || (t >= Q_P2 && t < Q_L1)) {
            const int pl = (t < Q_L0) ? 1 : 2;
            const int c = (t < Q_L0) ? t : (t - Q_P2);
            const size_t slab = (size_t)D_DIM * D_DIM / 4;
            prep_slab(pmu, prho, peps, (size_t)pl * slab, slab,
                      (size_t)c * 128 + tid, (size_t)PREP_CHUNKS * 128);
            __syncthreads();
            if (tid == 0) { __threadfence(); atomicAdd(&g_prep[pl - 1], 1); }
            continue;
        }

        // ---------- GEMM tile ----------
        int layer, tile, a_sel, c_sel, fuse_out;
        if (t < Q_P2)      { layer = 0; tile = t - Q_L0; a_sel = 0; c_sel = 1; fuse_out = 0; }
        else if (t < Q_L2) { layer = 1; tile = t - Q_L1; a_sel = 1; c_sel = 0; fuse_out = 0; }
        else               { layer = 2; tile = t - Q_L2; a_sel = 0; c_sel = 1; fuse_out = 1; }

        const int m0 = (tile >> 4) * BM;
        const int n0 = (tile & 15) * BN;

        // dependency check (should be pre-satisfied by queue order; spin is a safety net)
        if (tid == 0 && layer > 0) {
            volatile int* pp = &g_prep[layer - 1];
            volatile int* pb = &g_band[layer - 1][m0 >> 7];
            while (*pp < PREP_CHUNKS || *pb < 16) __nanosleep(64);
            __threadfence();
        }
        __syncthreads();

        const __nv_bfloat16* Ahi = g_ahi[a_sel];
        const __nv_bfloat16* Alo = g_alo[a_sel];
        const __nv_bfloat16* Whi = g_Whi + (size_t)layer * D_DIM * D_DIM;
        const __nv_bfloat16* Wlo = g_Wlo + (size_t)layer * D_DIM * D_DIM;
        const float* bias = g_bias + layer * D_DIM;
        __nv_bfloat16* Chi = g_ahi[c_sel];
        __nv_bfloat16* Clo = g_alo[c_sel];

        const __nv_bfloat16* gAhi = Ahi + (size_t)(m0 + lrow) * D_DIM + lc * 8;
        const __nv_bfloat16* gAlo = Alo + (size_t)(m0 + lrow) * D_DIM + lc * 8;
        const __nv_bfloat16* gWhi = Whi + (size_t)(n0 + lrow) * D_DIM + lc * 8;
        const __nv_bfloat16* gWlo = Wlo + (size_t)(n0 + lrow) * D_DIM + lc * 8;

        float acc[4][8][4];
#pragma unroll
        for (int i = 0; i < 4; i++)
#pragma unroll
            for (int j = 0; j < 8; j++)
#pragma unroll
                for (int r = 0; r < 4; r++) acc[i][j][r] = 0.0f;

#define LOAD_STAGE(stage_idx, kt_) do {                                              \
        const uint32_t so = sbase + (uint32_t)(stage_idx) * STAGE_B;                 \
        const size_t ko = (size_t)(kt_) * BK;                                        \
        _Pragma("unroll")                                                            \
        for (int p = 0; p < 4; p++) {                                                \
            const uint32_t d = so + dst_off + p * 2048;                              \
            const size_t g = ko + (size_t)p * 32 * D_DIM;                            \
            CP_ASYNC16(d,                gAhi + g);                                  \
            CP_ASYNC16(d + PLANE_B,      gAlo + g);                                  \
            CP_ASYNC16(d + 2 * PLANE_B,  gWhi + g);                                  \
            CP_ASYNC16(d + 3 * PLANE_B,  gWlo + g);                                  \
        }                                                                            \
        CP_COMMIT();                                                                 \
    } while (0)

        LOAD_STAGE(0, 0);
        LOAD_STAGE(1, 1);

        int buf = 0, pbuf = 2;
#pragma unroll 1
        for (int kt = 0; kt < NKT; kt++) {
            if (kt + 1 < NKT) { CP_WAIT(1); } else { CP_WAIT(0); }
            __syncthreads();
            if (kt + 2 < NKT) LOAD_STAGE(pbuf, kt + 2);

            const uint32_t st = sbase + (uint32_t)buf * STAGE_B;
            const uint32_t sa_hi = st;
            const uint32_t sa_lo = st + PLANE_B;
            const uint32_t sb_hi = st + 2 * PLANE_B;
            const uint32_t sb_lo = st + 3 * PLANE_B;

#pragma unroll
            for (int s = 0; s < 2; s++) {
                const uint32_t pa = (uint32_t)((((s << 1) | a_half) ^ a_sw) * 16);
                const uint32_t pb = (uint32_t)((((s << 1) | b_half) ^ b_sw) * 16);
                uint32_t ah[4][4], al[4][4], bh[4][4], bl[4][4];

#pragma unroll
                for (int mt = 0; mt < 4; mt++) {
                    const uint32_t ao = a_base + pa + mt * 1024;
                    LDSM4(ah[mt][0], ah[mt][1], ah[mt][2], ah[mt][3], sa_hi + ao);
                }
#pragma unroll
                for (int nt2 = 0; nt2 < 4; nt2++) {
                    const uint32_t bo = b_base + pb + nt2 * 1024;
                    LDSM4(bh[nt2][0], bh[nt2][1], bh[nt2][2], bh[nt2][3], sb_hi + bo);
                    LDSM4(bl[nt2][0], bl[nt2][1], bl[nt2][2], bl[nt2][3], sb_lo + bo);
                }

                // sweep 1: hi*hi
#pragma unroll
                for (int mt = 0; mt < 4; mt++)
#pragma unroll
                    for (int nt = 0; nt < 8; nt++) {
                        float* c = acc[mt][nt];
                        const int t2 = nt >> 1, j = (nt & 1) * 2;
                        mma_bf16(c[0], c[1], c[2], c[3],
                                 ah[mt][0], ah[mt][1], ah[mt][2], ah[mt][3],
                                 bh[t2][j], bh[t2][j + 1]);
                    }

#pragma unroll
                for (int mt = 0; mt < 4; mt++) {
                    const uint32_t ao = a_base + pa + mt * 1024;
                    LDSM4(al[mt][0], al[mt][1], al[mt][2], al[mt][3], sa_lo + ao);
                }

                // sweep 2: hi*lo
#pragma unroll
                for (int mt = 0; mt < 4; mt++)
#pragma unroll
                    for (int nt = 0; nt < 8; nt++) {
                        float* c = acc[mt][nt];
                        const int t2 = nt >> 1, j = (nt & 1) * 2;
                        mma_bf16(c[0], c[1], c[2], c[3],
                                 ah[mt][0], ah[mt][1], ah[mt][2], ah[mt][3],
                                 bl[t2][j], bl[t2][j + 1]);
                    }

                // sweep 3: lo*hi
#pragma unroll
                for (int mt = 0; mt < 4; mt++)
#pragma unroll
                    for (int nt = 0; nt < 8; nt++) {
                        float* c = acc[mt][nt];
                        const int t2 = nt >> 1, j = (nt & 1) * 2;
                        mma_bf16(c[0], c[1], c[2], c[3],
                                 al[mt][0], al[mt][1], al[mt][2], al[mt][3],
                                 bh[t2][j], bh[t2][j + 1]);
                    }
            }
            buf = (buf == 2) ? 0 : buf + 1;
            pbuf = (pbuf == 2) ? 0 : pbuf + 1;
        }

        // ---- epilogue ----
        float bv[8][2];
#pragma unroll
        for (int nt = 0; nt < 8; nt++) {
            const int col = n0 + warp_n + nt * 8 + tig * 2;
            bv[nt][0] = bias[col];
            bv[nt][1] = bias[col + 1];
        }

        if (fuse_out) {
            float wv[8][2];
#pragma unroll
            for (int nt = 0; nt < 8; nt++) {
                const int col = n0 + warp_n + nt * 8 + tig * 2;
                wv[nt][0] = g_wo[col];
                wv[nt][1] = g_wo[col + 1];
            }
#pragma unroll
            for (int mt = 0; mt < 4; mt++) {
#pragma unroll
                for (int half = 0; half < 2; half++) {
                    float s = 0.0f;
#pragma unroll
                    for (int nt = 0; nt < 8; nt++) {
                        float o0 = fmaxf(acc[mt][nt][half * 2 + 0] + bv[nt][0], 0.0f);
                        float o1 = fmaxf(acc[mt][nt][half * 2 + 1] + bv[nt][1], 0.0f);
                        s = fmaf(o0, wv[nt][0], s);
                        s = fmaf(o1, wv[nt][1], s);
                    }
                    s += __shfl_xor_sync(0xFFFFFFFFu, s, 1);
                    s += __shfl_xor_sync(0xFFFFFFFFu, s, 2);
                    if (tig == 0) {
                        const int row = m0 + warp_m + mt * 16 + gid + half * 8;
                        atomicAdd(out + row, s);
                    }
                }
            }
        } else {
#pragma unroll
            for (int mt = 0; mt < 4; mt++) {
                const int r0 = m0 + warp_m + mt * 16 + gid;
#pragma unroll
                for (int half = 0; half < 2; half++) {
                    const size_t rb = (size_t)(r0 + half * 8) * D_DIM + n0 + warp_n;
#pragma unroll
                    for (int nt = 0; nt < 8; nt++) {
                        float o0 = fmaxf(acc[mt][nt][half * 2 + 0] + bv[nt][0], 0.0f);
                        float o1 = fmaxf(acc[mt][nt][half * 2 + 1] + bv[nt][1], 0.0f);
                        __nv_bfloat16 h0, l0, h1, l1;
                        split_bf16(o0, h0, l0);
                        split_bf16(o1, h1, l1);
                        __nv_bfloat162 hp; hp.x = h0; hp.y = h1;
                        __nv_bfloat162 lp; lp.x = l0; lp.y = l1;
                        *reinterpret_cast<__nv_bfloat162*>(Chi + rb + nt * 8 + tig * 2) = hp;
                        *reinterpret_cast<__nv_bfloat162*>(Clo + rb + nt * 8 + tig * 2) = lp;
                    }
                }
            }
            __syncthreads();
            if (tid == 0) { __threadfence(); atomicAdd(&g_band[layer][m0 >> 7], 1); }
        }
    }
}

// ---------------- Merged prologue: W0 prep + input split + small params + sched reset ----
#define PRO_W0 1024
#define PRO_SX 1024
#define PRO_SM 16
#define PRO_TOTAL (PRO_W0 + PRO_SX + PRO_SM)

__global__ void __launch_bounds__(256) prologue(
    const float4* __restrict__ wmu, const float4* __restrict__ wrho,
    const float4* __restrict__ weps,
    const float4* __restrict__ x,
    const float* __restrict__ bmu, const float* __restrict__ brho,
    const float* __restrict__ beps,
    const float* __restrict__ womu, const float* __restrict__ worho,
    const float* __restrict__ woeps,
    const float* __restrict__ bomu, const float* __restrict__ borho,
    const float* __restrict__ boeps,
    float* __restrict__ out)
{
    const int b = blockIdx.x;
    const int tid = threadIdx.x;

    if (b < PRO_W0) {
        const size_t n = (size_t)D_DIM * D_DIM / 4;
        prep_slab(wmu, wrho, weps, 0, n,
                  (size_t)b * 256 + tid, (size_t)PRO_W0 * 256);
    } else if (b < PRO_W0 + PRO_SX) {
        const size_t n = (size_t)B_DIM * D_DIM / 4;
        for (size_t i = (size_t)(b - PRO_W0) * 256 + tid; i < n;
             i += (size_t)PRO_SX * 256) {
            float4 v = x[i];
            __nv_bfloat16 h[4], l[4];
            split_bf16(v.x, h[0], l[0]);
            split_bf16(v.y, h[1], l[1]);
            split_bf16(v.z, h[2], l[2]);
            split_bf16(v.w, h[3], l[3]);
            reinterpret_cast<ulonglong1*>(g_ahi[0])[i].x =
                *reinterpret_cast<unsigned long long*>(h);
            reinterpret_cast<ulonglong1*>(g_alo[0])[i].x =
                *reinterpret_cast<unsigned long long*>(l);
        }
    } else {
        const int t = (b - PRO_W0 - PRO_SX) * 256 + tid;
        const int stride = PRO_SM * 256;
        for (int i = t; i < H_LAYERS * D_DIM; i += stride)
            g_bias[i] = fmaf(beps[i], softplus_fast(brho[i]), bmu[i]);
        for (int i = t; i < D_DIM; i += stride)
            g_wo[i] = fmaf(woeps[i], softplus_fast(worho[i]), womu[i]);
        const float bo = fmaf(boeps[0], softplus_fast(borho[0]), bomu[0]);
        for (int i = t; i < B_DIM; i += stride)
            out[i] = bo;
        // scheduler reset (fresh per launch / graph replay)
        if (t == 0) { g_ticket = 0; g_prep[0] = 0; g_prep[1] = 0; }
        for (int i = t; i < 64; i += stride)
            (&g_band[0][0])[i] = 0;
    }
}

// ---------------- Launch ----------------
extern "C" void kernel_launch(void* const* d_in, const int* in_sizes, int n_in,
                              void* d_out, int out_size)
{
    (void)in_sizes; (void)n_in; (void)out_size;
    const float4* x = (const float4*)d_in[0];
    const float4* wmu = (const float4*)d_in[1];
    const float4* wrho = (const float4*)d_in[2];
    const float4* weps = (const float4*)d_in[9];
    float* out = (float*)d_out;

    static int smem_set = 0;
    if (!smem_set) {
        cudaFuncSetAttribute(fused_net, cudaFuncAttributeMaxDynamicSharedMemorySize,
                             SMEM_TOTAL);
        smem_set = 1;
    }

    prologue<<<PRO_TOTAL, 256>>>(
        wmu, wrho, weps, x,
        (const float*)d_in[3], (const float*)d_in[4], (const float*)d_in[10],
        (const float*)d_in[5], (const float*)d_in[6], (const float*)d_in[11],
        (const float*)d_in[7], (const float*)d_in[8], (const float*)d_in[12],
        out);

    fused_net<<<NPERSIST, 128, SMEM_TOTAL>>>(wmu, wrho, weps, out);
}

// round 15
// speedup vs baseline: 1.6520x; 1.6520x over previous
#include <cuda_runtime.h>
#include <cuda_fp16.h>
#include <cstdint>
#include <cstddef>

// ---------------- Problem dims ----------------
#define D_DIM 2048
#define B_DIM 4096
#define H_LAYERS 3

// ---------------- Device scratch ----------------
// Weights: split fp16 hi/lo planes. Activations: single fp16 plane (asymmetric split).
__device__ __half g_Whi[(size_t)H_LAYERS * D_DIM * D_DIM];
__device__ __half g_Wlo[(size_t)H_LAYERS * D_DIM * D_DIM];
__device__ float g_bias[H_LAYERS * D_DIM];
__device__ float g_wo[D_DIM];
__device__ __half g_a[2][(size_t)B_DIM * D_DIM];

// ---------------- helpers ----------------
__device__ __forceinline__ uint32_t smem_u32(const void* p) {
    uint32_t a;
    asm("{ .reg .u64 t; cvta.to.shared.u64 t, %1; cvt.u32.u64 %0, t; }" : "=r"(a) : "l"(p));
    return a;
}

#define CP_ASYNC16(dst, src) \
    asm volatile("cp.async.cg.shared.global [%0], [%1], 16;" :: "r"(dst), "l"(src) : "memory")
#define CP_COMMIT() asm volatile("cp.async.commit_group;" ::: "memory")
#define CP_WAIT(n)  asm volatile("cp.async.wait_group %0;" :: "n"(n) : "memory")

#define LDSM4(r0, r1, r2, r3, addr) \
    asm volatile("ldmatrix.sync.aligned.m8n8.x4.shared.b16 {%0,%1,%2,%3}, [%4];" \
                 : "=r"(r0), "=r"(r1), "=r"(r2), "=r"(r3) : "r"(addr))

__device__ __forceinline__ void mma_fp16(float& c0, float& c1, float& c2, float& c3,
                                         uint32_t a0, uint32_t a1, uint32_t a2, uint32_t a3,
                                         uint32_t b0, uint32_t b1) {
    asm volatile(
        "mma.sync.aligned.m16n8k16.row.col.f32.f16.f16.f32 "
        "{%0,%1,%2,%3}, {%4,%5,%6,%7}, {%8,%9}, {%0,%1,%2,%3};"
        : "+f"(c0), "+f"(c1), "+f"(c2), "+f"(c3)
        : "r"(a0), "r"(a1), "r"(a2), "r"(a3), "r"(b0), "r"(b1));
}

// MUFU-free e^x (poly 2^r + exponent bit trick)
__device__ __forceinline__ float fast_exp(float x) {
    float y = x * 1.4426950408889634f;
    float f = floorf(y);
    float r = y - f;
    float p = 1.53989903e-4f;
    p = fmaf(p, r, 1.33335581e-3f);
    p = fmaf(p, r, 9.61817249e-3f);
    p = fmaf(p, r, 5.55041087e-2f);
    p = fmaf(p, r, 2.40226507e-1f);
    p = fmaf(p, r, 6.93147181e-1f);
    p = fmaf(p, r, 1.0f);
    int i = (int)f;
    if (i < -126) i = -126;
    return p * __int_as_float((i + 127) << 23);
}

__device__ __forceinline__ float softplus_fast(float x) {
    float t = fast_exp(x);
    if (t < 0.25f) {
        float p = fmaf(t, -0.125f, 0.14285714285714285f);
        p = fmaf(t, p, -0.16666666666666666f);
        p = fmaf(t, p, 0.2f);
        p = fmaf(t, p, -0.25f);
        p = fmaf(t, p, 0.3333333333333333f);
        p = fmaf(t, p, -0.5f);
        p = fmaf(t, p, 1.0f);
        return t * p;
    }
    return 0.6931471805599453f * log2f(1.0f + t);
}

__device__ __forceinline__ void split_fp16(float v, __half& hi, __half& lo) {
    hi = __float2half_rn(v);
    lo = __float2half_rn(v - __half2float(hi));
}

// prep body: materialize split fp16 weights for one layer slab
__device__ __forceinline__ void prep_slab(const float4* __restrict__ mu,
                                          const float4* __restrict__ rho,
                                          const float4* __restrict__ eps,
                                          size_t off, size_t n,
                                          size_t start, size_t stride)
{
    for (size_t i = start; i < n; i += stride) {
        float4 m = mu[off + i], r = rho[off + i], e = eps[off + i];
        float w0 = fmaf(e.x, softplus_fast(r.x), m.x);
        float w1 = fmaf(e.y, softplus_fast(r.y), m.y);
        float w2 = fmaf(e.z, softplus_fast(r.z), m.z);
        float w3 = fmaf(e.w, softplus_fast(r.w), m.w);
        __half h[4], l[4];
        split_fp16(w0, h[0], l[0]);
        split_fp16(w1, h[1], l[1]);
        split_fp16(w2, h[2], l[2]);
        split_fp16(w3, h[3], l[3]);
        reinterpret_cast<ulonglong1*>(g_Whi)[off + i].x =
            *reinterpret_cast<unsigned long long*>(h);
        reinterpret_cast<ulonglong1*>(g_Wlo)[off + i].x =
            *reinterpret_cast<unsigned long long*>(l);
    }
}

// ---------------- GEMM config ----------------
#define BM 128
#define BN 128
#define BK 32
#define NKT (D_DIM / BK)          // 64
#define NTILES 512
#define PREP_CTAS 64
// Compact layout: 64B rows, XOR swizzle pc = c ^ ((row>>1)&3)
#define PLANE_B 8192              // 128 rows * 64B
#define STAGE_B (3 * PLANE_B)     // A, Whi, Wlo = 24576 B
#define NSTAGE 4
#define SMEM_TOTAL (NSTAGE * STAGE_B)   // 98304 B -> 2 CTAs/SM

__global__ void __launch_bounds__(128, 2)
gemm_split_relu(int a_sel, int layer, int c_sel, int fuse_out,
                const float4* __restrict__ pmu, const float4* __restrict__ prho,
                const float4* __restrict__ peps, int prep_layer,
                float* __restrict__ out)
{
    extern __shared__ __half smem[];

    const int bid = blockIdx.x;
    const int tid = threadIdx.x;

    if (bid >= NTILES) {
        const size_t slab = (size_t)D_DIM * D_DIM / 4;
        const size_t off = (size_t)prep_layer * slab;
        const size_t start = (size_t)(bid - NTILES) * 128 + tid;
        prep_slab(pmu, prho, peps, off, slab, start, (size_t)PREP_CTAS * 128);
        return;
    }

    const int wid = tid >> 5, lane = tid & 31;
    const int gid = lane >> 2, tig = lane & 3;

    const __half* A = g_a[a_sel];
    const __half* Whi = g_Whi + (size_t)layer * D_DIM * D_DIM;
    const __half* Wlo = g_Wlo + (size_t)layer * D_DIM * D_DIM;
    const float* bias = g_bias + layer * D_DIM;
    __half* C = g_a[c_sel];

    const int m0 = (bid >> 4) * BM;
    const int n0 = (bid & 15) * BN;

    // ---- loader: 128 threads = 32 rows x 4 chunks per pass, 4 passes per plane ----
    const int lrow = tid >> 2;
    const int lc = tid & 3;
    const int pc = lc ^ ((lrow >> 1) & 3);
    const uint32_t sbase = smem_u32(smem);
    const uint32_t dst_off = (uint32_t)(lrow * 64 + pc * 16);

    const __half* gA   = A   + (size_t)(m0 + lrow) * D_DIM + lc * 8;
    const __half* gWhi = Whi + (size_t)(n0 + lrow) * D_DIM + lc * 8;
    const __half* gWlo = Wlo + (size_t)(n0 + lrow) * D_DIM + lc * 8;

    // ---- warp tiling: 2(m) x 2(n); warp tile 64x64 ----
    const int warp_m = (wid & 1) * 64;
    const int warp_n = (wid >> 1) * 64;

    const int a_row = warp_m + ((lane >> 3) & 1) * 8 + (lane & 7);
    const uint32_t a_base = (uint32_t)(a_row * 64);
    const int a_sw = (a_row >> 1) & 3;
    const int a_half = lane >> 4;
    const int b_row = warp_n + (lane >> 4) * 8 + (lane & 7);
    const uint32_t b_base = (uint32_t)(b_row * 64);
    const int b_sw = (b_row >> 1) & 3;
    const int b_half = (lane >> 3) & 1;

    float acc[4][8][4];
#pragma unroll
    for (int i = 0; i < 4; i++)
#pragma unroll
        for (int j = 0; j < 8; j++)
#pragma unroll
            for (int r = 0; r < 4; r++) acc[i][j][r] = 0.0f;

#define LOAD_STAGE(stage_idx, kt_) do {                                              \
        const uint32_t so = sbase + (uint32_t)(stage_idx) * STAGE_B;                 \
        const size_t ko = (size_t)(kt_) * BK;                                        \
        _Pragma("unroll")                                                            \
        for (int p = 0; p < 4; p++) {                                                \
            const uint32_t d = so + dst_off + p * 2048;                              \
            const size_t g = ko + (size_t)p * 32 * D_DIM;                            \
            CP_ASYNC16(d,                gA + g);                                    \
            CP_ASYNC16(d + PLANE_B,      gWhi + g);                                  \
            CP_ASYNC16(d + 2 * PLANE_B,  gWlo + g);                                  \
        }                                                                            \
        CP_COMMIT();                                                                 \
    } while (0)

    LOAD_STAGE(0, 0);
    LOAD_STAGE(1, 1);
    LOAD_STAGE(2, 2);

    int buf = 0, pbuf = 3;
#pragma unroll 1
    for (int kt = 0; kt < NKT; kt++) {
        if (kt < NKT - 2)       { CP_WAIT(2); }
        else if (kt == NKT - 2) { CP_WAIT(1); }
        else                    { CP_WAIT(0); }
        __syncthreads();
        if (kt + 3 < NKT) LOAD_STAGE(pbuf, kt + 3);

        const uint32_t st = sbase + (uint32_t)buf * STAGE_B;
        const uint32_t sa    = st;
        const uint32_t sb_hi = st + PLANE_B;
        const uint32_t sb_lo = st + 2 * PLANE_B;

#pragma unroll
        for (int s = 0; s < 2; s++) {
            const uint32_t pa = (uint32_t)((((s << 1) | a_half) ^ a_sw) * 16);
            const uint32_t pb = (uint32_t)((((s << 1) | b_half) ^ b_sw) * 16);
            uint32_t ah[4][4], bh[4][4], bl[4][4];

#pragma unroll
            for (int mt = 0; mt < 4; mt++) {
                const uint32_t ao = a_base + pa + mt * 1024;
                LDSM4(ah[mt][0], ah[mt][1], ah[mt][2], ah[mt][3], sa + ao);
            }
#pragma unroll
            for (int nt2 = 0; nt2 < 4; nt2++) {
                const uint32_t bo = b_base + pb + nt2 * 1024;
                LDSM4(bh[nt2][0], bh[nt2][1], bh[nt2][2], bh[nt2][3], sb_hi + bo);
                LDSM4(bl[nt2][0], bl[nt2][1], bl[nt2][2], bl[nt2][3], sb_lo + bo);
            }

            // sweep 1: a * W_hi
#pragma unroll
            for (int mt = 0; mt < 4; mt++)
#pragma unroll
                for (int nt = 0; nt < 8; nt++) {
                    float* c = acc[mt][nt];
                    const int t2 = nt >> 1, j = (nt & 1) * 2;
                    mma_fp16(c[0], c[1], c[2], c[3],
                             ah[mt][0], ah[mt][1], ah[mt][2], ah[mt][3],
                             bh[t2][j], bh[t2][j + 1]);
                }

            // sweep 2: a * W_lo
#pragma unroll
            for (int mt = 0; mt < 4; mt++)
#pragma unroll
                for (int nt = 0; nt < 8; nt++) {
                    float* c = acc[mt][nt];
                    const int t2 = nt >> 1, j = (nt & 1) * 2;
                    mma_fp16(c[0], c[1], c[2], c[3],
                             ah[mt][0], ah[mt][1], ah[mt][2], ah[mt][3],
                             bl[t2][j], bl[t2][j + 1]);
                }
        }
        buf = (buf + 1) & 3;
        pbuf = (pbuf + 1) & 3;
    }

    // ---- epilogue ----
    float bv[8][2];
#pragma unroll
    for (int nt = 0; nt < 8; nt++) {
        const int col = n0 + warp_n + nt * 8 + tig * 2;
        bv[nt][0] = bias[col];
        bv[nt][1] = bias[col + 1];
    }

    if (fuse_out) {
        float wv[8][2];
#pragma unroll
        for (int nt = 0; nt < 8; nt++) {
            const int col = n0 + warp_n + nt * 8 + tig * 2;
            wv[nt][0] = g_wo[col];
            wv[nt][1] = g_wo[col + 1];
        }
#pragma unroll
        for (int mt = 0; mt < 4; mt++) {
#pragma unroll
            for (int half = 0; half < 2; half++) {
                float s = 0.0f;
#pragma unroll
                for (int nt = 0; nt < 8; nt++) {
                    float o0 = fmaxf(acc[mt][nt][half * 2 + 0] + bv[nt][0], 0.0f);
                    float o1 = fmaxf(acc[mt][nt][half * 2 + 1] + bv[nt][1], 0.0f);
                    s = fmaf(o0, wv[nt][0], s);
                    s = fmaf(o1, wv[nt][1], s);
                }
                s += __shfl_xor_sync(0xFFFFFFFFu, s, 1);
                s += __shfl_xor_sync(0xFFFFFFFFu, s, 2);
                if (tig == 0) {
                    const int row = m0 + warp_m + mt * 16 + gid + half * 8;
                    atomicAdd(out + row, s);
                }
            }
        }
    } else {
#pragma unroll
        for (int mt = 0; mt < 4; mt++) {
            const int r0 = m0 + warp_m + mt * 16 + gid;
#pragma unroll
            for (int half = 0; half < 2; half++) {
                const size_t rb = (size_t)(r0 + half * 8) * D_DIM + n0 + warp_n;
#pragma unroll
                for (int nt = 0; nt < 8; nt++) {
                    float o0 = fmaxf(acc[mt][nt][half * 2 + 0] + bv[nt][0], 0.0f);
                    float o1 = fmaxf(acc[mt][nt][half * 2 + 1] + bv[nt][1], 0.0f);
                    __half2 hp = __floats2half2_rn(o0, o1);
                    *reinterpret_cast<__half2*>(C + rb + nt * 8 + tig * 2) = hp;
                }
            }
        }
    }
}

// ---------------- Merged prologue: W0 prep + input convert + small params ----------------
#define PRO_W0 1024
#define PRO_SX 1024
#define PRO_SM 16
#define PRO_TOTAL (PRO_W0 + PRO_SX + PRO_SM)

__global__ void __launch_bounds__(256) prologue(
    const float4* __restrict__ wmu, const float4* __restrict__ wrho,
    const float4* __restrict__ weps,
    const float4* __restrict__ x,
    const float* __restrict__ bmu, const float* __restrict__ brho,
    const float* __restrict__ beps,
    const float* __restrict__ womu, const float* __restrict__ worho,
    const float* __restrict__ woeps,
    const float* __restrict__ bomu, const float* __restrict__ borho,
    const float* __restrict__ boeps,
    float* __restrict__ out)
{
    const int b = blockIdx.x;
    const int tid = threadIdx.x;

    if (b < PRO_W0) {
        const size_t n = (size_t)D_DIM * D_DIM / 4;
        prep_slab(wmu, wrho, weps, 0, n,
                  (size_t)b * 256 + tid, (size_t)PRO_W0 * 256);
    } else if (b < PRO_W0 + PRO_SX) {
        const size_t n = (size_t)B_DIM * D_DIM / 4;
        for (size_t i = (size_t)(b - PRO_W0) * 256 + tid; i < n;
             i += (size_t)PRO_SX * 256) {
            float4 v = x[i];
            __half h[4];
            h[0] = __float2half_rn(v.x);
            h[1] = __float2half_rn(v.y);
            h[2] = __float2half_rn(v.z);
            h[3] = __float2half_rn(v.w);
            reinterpret_cast<ulonglong1*>(g_a[0])[i].x =
                *reinterpret_cast<unsigned long long*>(h);
        }
    } else {
        const int t = (b - PRO_W0 - PRO_SX) * 256 + tid;
        const int stride = PRO_SM * 256;
        for (int i = t; i < H_LAYERS * D_DIM; i += stride)
            g_bias[i] = fmaf(beps[i], softplus_fast(brho[i]), bmu[i]);
        for (int i = t; i < D_DIM; i += stride)
            g_wo[i] = fmaf(woeps[i], softplus_fast(worho[i]), womu[i]);
        const float bo = fmaf(boeps[0], softplus_fast(borho[0]), bomu[0]);
        for (int i = t; i < B_DIM; i += stride)
            out[i] = bo;
    }
}

// ---------------- Launch ----------------
extern "C" void kernel_launch(void* const* d_in, const int* in_sizes, int n_in,
                              void* d_out, int out_size)
{
    (void)in_sizes; (void)n_in; (void)out_size;
    const float4* x = (const float4*)d_in[0];
    const float4* wmu = (const float4*)d_in[1];
    const float4* wrho = (const float4*)d_in[2];
    const float4* weps = (const float4*)d_in[9];
    float* out = (float*)d_out;

    static int smem_set = 0;
    if (!smem_set) {
        cudaFuncSetAttribute(gemm_split_relu, cudaFuncAttributeMaxDynamicSharedMemorySize,
                             SMEM_TOTAL);
        smem_set = 1;
    }

    prologue<<<PRO_TOTAL, 256>>>(
        wmu, wrho, weps, x,
        (const float*)d_in[3], (const float*)d_in[4], (const float*)d_in[10],
        (const float*)d_in[5], (const float*)d_in[6], (const float*)d_in[11],
        (const float*)d_in[7], (const float*)d_in[8], (const float*)d_in[12],
        out);

    // Layer 0: GEMM + hidden prep of W1
    gemm_split_relu<<<NTILES + PREP_CTAS, 128, SMEM_TOTAL>>>(
        0, 0, 1, 0, wmu, wrho, weps, 1, out);
    // Layer 1: GEMM + hidden prep of W2
    gemm_split_relu<<<NTILES + PREP_CTAS, 128, SMEM_TOTAL>>>(
        1, 1, 0, 0, wmu, wrho, weps, 2, out);
    // Layer 2: GEMM with fused output reduction
    gemm_split_relu<<<NTILES, 128, SMEM_TOTAL>>>(
        0, 2, 1, 1, wmu, wrho, weps, -1, out);
}

// round 16
// speedup vs baseline: 1.6766x; 1.0149x over previous
#include <cuda_runtime.h>
#include <cuda_fp16.h>
#include <cstdint>
#include <cstddef>

// ---------------- Problem dims ----------------
#define D_DIM 2048
#define B_DIM 4096
#define H_LAYERS 3

// ---------------- Device scratch ----------------
__device__ __half g_Whi[(size_t)H_LAYERS * D_DIM * D_DIM];
__device__ __half g_Wlo[(size_t)H_LAYERS * D_DIM * D_DIM];
__device__ float g_bias[H_LAYERS * D_DIM];
__device__ float g_wo[D_DIM];
__device__ __half g_a[2][(size_t)B_DIM * D_DIM];

// ---------------- helpers ----------------
__device__ __forceinline__ uint32_t smem_u32(const void* p) {
    uint32_t a;
    asm("{ .reg .u64 t; cvta.to.shared.u64 t, %1; cvt.u32.u64 %0, t; }" : "=r"(a) : "l"(p));
    return a;
}

#define CP_ASYNC16(dst, src) \
    asm volatile("cp.async.cg.shared.global [%0], [%1], 16;" :: "r"(dst), "l"(src) : "memory")
#define CP_COMMIT() asm volatile("cp.async.commit_group;" ::: "memory")
#define CP_WAIT(n)  asm volatile("cp.async.wait_group %0;" :: "n"(n) : "memory")

#define LDSM4(r0, r1, r2, r3, addr) \
    asm volatile("ldmatrix.sync.aligned.m8n8.x4.shared.b16 {%0,%1,%2,%3}, [%4];" \
                 : "=r"(r0), "=r"(r1), "=r"(r2), "=r"(r3) : "r"(addr))

__device__ __forceinline__ void mma_fp16(float& c0, float& c1, float& c2, float& c3,
                                         uint32_t a0, uint32_t a1, uint32_t a2, uint32_t a3,
                                         uint32_t b0, uint32_t b1) {
    asm volatile(
        "mma.sync.aligned.m16n8k16.row.col.f32.f16.f16.f32 "
        "{%0,%1,%2,%3}, {%4,%5,%6,%7}, {%8,%9}, {%0,%1,%2,%3};"
        : "+f"(c0), "+f"(c1), "+f"(c2), "+f"(c3)
        : "r"(a0), "r"(a1), "r"(a2), "r"(a3), "r"(b0), "r"(b1));
}

// MUFU-free e^x (poly 2^r + exponent bit trick)
__device__ __forceinline__ float fast_exp(float x) {
    float y = x * 1.4426950408889634f;
    float f = floorf(y);
    float r = y - f;
    float p = 1.53989903e-4f;
    p = fmaf(p, r, 1.33335581e-3f);
    p = fmaf(p, r, 9.61817249e-3f);
    p = fmaf(p, r, 5.55041087e-2f);
    p = fmaf(p, r, 2.40226507e-1f);
    p = fmaf(p, r, 6.93147181e-1f);
    p = fmaf(p, r, 1.0f);
    int i = (int)f;
    if (i < -126) i = -126;
    return p * __int_as_float((i + 127) << 23);
}

__device__ __forceinline__ float softplus_fast(float x) {
    float t = fast_exp(x);
    if (t < 0.25f) {
        float p = fmaf(t, -0.125f, 0.14285714285714285f);
        p = fmaf(t, p, -0.16666666666666666f);
        p = fmaf(t, p, 0.2f);
        p = fmaf(t, p, -0.25f);
        p = fmaf(t, p, 0.3333333333333333f);
        p = fmaf(t, p, -0.5f);
        p = fmaf(t, p, 1.0f);
        return t * p;
    }
    return 0.6931471805599453f * log2f(1.0f + t);
}

__device__ __forceinline__ void split_fp16(float v, __half& hi, __half& lo) {
    hi = __float2half_rn(v);
    lo = __float2half_rn(v - __half2float(hi));
}

__device__ __forceinline__ void prep_slab(const float4* __restrict__ mu,
                                          const float4* __restrict__ rho,
                                          const float4* __restrict__ eps,
                                          size_t off, size_t n,
                                          size_t start, size_t stride)
{
    for (size_t i = start; i < n; i += stride) {
        float4 m = mu[off + i], r = rho[off + i], e = eps[off + i];
        float w0 = fmaf(e.x, softplus_fast(r.x), m.x);
        float w1 = fmaf(e.y, softplus_fast(r.y), m.y);
        float w2 = fmaf(e.z, softplus_fast(r.z), m.z);
        float w3 = fmaf(e.w, softplus_fast(r.w), m.w);
        __half h[4], l[4];
        split_fp16(w0, h[0], l[0]);
        split_fp16(w1, h[1], l[1]);
        split_fp16(w2, h[2], l[2]);
        split_fp16(w3, h[3], l[3]);
        reinterpret_cast<ulonglong1*>(g_Whi)[off + i].x =
            *reinterpret_cast<unsigned long long*>(h);
        reinterpret_cast<ulonglong1*>(g_Wlo)[off + i].x =
            *reinterpret_cast<unsigned long long*>(l);
    }
}

// ---------------- GEMM config ----------------
#define BM 128
#define BN 128
#define BK 32
#define NKT (D_DIM / BK)          // 64
#define NTILES 512
#define PREP_CTAS 64
#define PLANE_B 8192              // 128 rows * 64B
#define STAGE_B (3 * PLANE_B)     // A, Whi, Wlo = 24576 B
#define NSTAGE 4
#define SMEM_TOTAL (NSTAGE * STAGE_B)   // 98304 B -> 2 CTAs/SM

__global__ void __launch_bounds__(128, 2)
gemm_split_relu(int a_sel, int layer, int c_sel, int fuse_out,
                const float4* __restrict__ pmu, const float4* __restrict__ prho,
                const float4* __restrict__ peps, int prep_layer,
                float* __restrict__ out)
{
    extern __shared__ __half smem[];

    const int bid = blockIdx.x;
    const int tid = threadIdx.x;

    if (bid >= NTILES) {
        const size_t slab = (size_t)D_DIM * D_DIM / 4;
        const size_t off = (size_t)prep_layer * slab;
        const size_t start = (size_t)(bid - NTILES) * 128 + tid;
        prep_slab(pmu, prho, peps, off, slab, start, (size_t)PREP_CTAS * 128);
        return;
    }

    const int wid = tid >> 5, lane = tid & 31;
    const int gid = lane >> 2, tig = lane & 3;

    const __half* A = g_a[a_sel];
    const __half* Whi = g_Whi + (size_t)layer * D_DIM * D_DIM;
    const __half* Wlo = g_Wlo + (size_t)layer * D_DIM * D_DIM;
    const float* bias = g_bias + layer * D_DIM;
    __half* C = g_a[c_sel];

    const int m0 = (bid >> 4) * BM;
    const int n0 = (bid & 15) * BN;

    // ---- loader ----
    const int lrow = tid >> 2;
    const int lc = tid & 3;
    const int pc = lc ^ ((lrow >> 1) & 3);
    const uint32_t sbase = smem_u32(smem);
    const uint32_t dst_off = (uint32_t)(lrow * 64 + pc * 16);

    const __half* gA   = A   + (size_t)(m0 + lrow) * D_DIM + lc * 8;
    const __half* gWhi = Whi + (size_t)(n0 + lrow) * D_DIM + lc * 8;
    const __half* gWlo = Wlo + (size_t)(n0 + lrow) * D_DIM + lc * 8;

    // ---- warp tiling: 2(m) x 2(n); warp tile 64x64 ----
    const int warp_m = (wid & 1) * 64;
    const int warp_n = (wid >> 1) * 64;

    const int a_row = warp_m + ((lane >> 3) & 1) * 8 + (lane & 7);
    const uint32_t a_base = (uint32_t)(a_row * 64);
    const int a_sw = (a_row >> 1) & 3;
    const int a_half = lane >> 4;
    const int b_row = warp_n + (lane >> 4) * 8 + (lane & 7);
    const uint32_t b_base = (uint32_t)(b_row * 64);
    const int b_sw = (b_row >> 1) & 3;
    const int b_half = (lane >> 3) & 1;

    float acc[4][8][4];
#pragma unroll
    for (int i = 0; i < 4; i++)
#pragma unroll
        for (int j = 0; j < 8; j++)
#pragma unroll
            for (int r = 0; r < 4; r++) acc[i][j][r] = 0.0f;

#define LOAD_STAGE(stage_idx, kt_) do {                                              \
        const uint32_t so = sbase + (uint32_t)(stage_idx) * STAGE_B;                 \
        const size_t ko = (size_t)(kt_) * BK;                                        \
        _Pragma("unroll")                                                            \
        for (int p = 0; p < 4; p++) {                                                \
            const uint32_t d = so + dst_off + p * 2048;                              \
            const size_t g = ko + (size_t)p * 32 * D_DIM;                            \
            CP_ASYNC16(d,                gA + g);                                    \
            CP_ASYNC16(d + PLANE_B,      gWhi + g);                                  \
            CP_ASYNC16(d + 2 * PLANE_B,  gWlo + g);                                  \
        }                                                                            \
        CP_COMMIT();                                                                 \
    } while (0)

    // prefetch distance 2: stage for kt is loaded at kt-2
    LOAD_STAGE(0, 0);
    LOAD_STAGE(1, 1);

#pragma unroll 1
    for (int kt = 0; kt < NKT; kt++) {
        if (kt + 1 < NKT) { CP_WAIT(1); } else { CP_WAIT(0); }
        // barrier only on even kt: stage (kt+2)&3 == (kt-2)&3, whose consumers
        // all finished before the previous even-kt barrier. Cross-thread cp.async
        // visibility at odd kt is covered by >= 1 full kt of compute (~2800 cyc)
        // between issue and first read (landing <= ~600 cyc).
        if ((kt & 1) == 0) __syncthreads();
        if (kt + 2 < NKT) LOAD_STAGE((kt + 2) & 3, kt + 2);

        const uint32_t st = sbase + (uint32_t)(kt & 3) * STAGE_B;
        const uint32_t sa    = st;
        const uint32_t sb_hi = st + PLANE_B;
        const uint32_t sb_lo = st + 2 * PLANE_B;

#pragma unroll
        for (int s = 0; s < 2; s++) {
            const uint32_t pa = (uint32_t)((((s << 1) | a_half) ^ a_sw) * 16);
            const uint32_t pb = (uint32_t)((((s << 1) | b_half) ^ b_sw) * 16);
            uint32_t ah[4][4], bh[4][4], bl[4][4];

#pragma unroll
            for (int mt = 0; mt < 4; mt++) {
                const uint32_t ao = a_base + pa + mt * 1024;
                LDSM4(ah[mt][0], ah[mt][1], ah[mt][2], ah[mt][3], sa + ao);
            }
#pragma unroll
            for (int nt2 = 0; nt2 < 4; nt2++) {
                const uint32_t bo = b_base + pb + nt2 * 1024;
                LDSM4(bh[nt2][0], bh[nt2][1], bh[nt2][2], bh[nt2][3], sb_hi + bo);
            }

            // sweep 1: a * W_hi
#pragma unroll
            for (int mt = 0; mt < 4; mt++)
#pragma unroll
                for (int nt = 0; nt < 8; nt++) {
                    float* c = acc[mt][nt];
                    const int t2 = nt >> 1, j = (nt & 1) * 2;
                    mma_fp16(c[0], c[1], c[2], c[3],
                             ah[mt][0], ah[mt][1], ah[mt][2], ah[mt][3],
                             bh[t2][j], bh[t2][j + 1]);
                }

            // B_lo fragments loaded late (lower live-set, spread crossbar burst)
#pragma unroll
            for (int nt2 = 0; nt2 < 4; nt2++) {
                const uint32_t bo = b_base + pb + nt2 * 1024;
                LDSM4(bl[nt2][0], bl[nt2][1], bl[nt2][2], bl[nt2][3], sb_lo + bo);
            }

            // sweep 2: a * W_lo
#pragma unroll
            for (int mt = 0; mt < 4; mt++)
#pragma unroll
                for (int nt = 0; nt < 8; nt++) {
                    float* c = acc[mt][nt];
                    const int t2 = nt >> 1, j = (nt & 1) * 2;
                    mma_fp16(c[0], c[1], c[2], c[3],
                             ah[mt][0], ah[mt][1], ah[mt][2], ah[mt][3],
                             bl[t2][j], bl[t2][j + 1]);
                }
        }
    }

    // ---- epilogue ----
    float bv[8][2];
#pragma unroll
    for (int nt = 0; nt < 8; nt++) {
        const int col = n0 + warp_n + nt * 8 + tig * 2;
        bv[nt][0] = bias[col];
        bv[nt][1] = bias[col + 1];
    }

    if (fuse_out) {
        float wv[8][2];
#pragma unroll
        for (int nt = 0; nt < 8; nt++) {
            const int col = n0 + warp_n + nt * 8 + tig * 2;
            wv[nt][0] = g_wo[col];
            wv[nt][1] = g_wo[col + 1];
        }
#pragma unroll
        for (int mt = 0; mt < 4; mt++) {
#pragma unroll
            for (int half = 0; half < 2; half++) {
                float s = 0.0f;
#pragma unroll
                for (int nt = 0; nt < 8; nt++) {
                    float o0 = fmaxf(acc[mt][nt][half * 2 + 0] + bv[nt][0], 0.0f);
                    float o1 = fmaxf(acc[mt][nt][half * 2 + 1] + bv[nt][1], 0.0f);
                    s = fmaf(o0, wv[nt][0], s);
                    s = fmaf(o1, wv[nt][1], s);
                }
                s += __shfl_xor_sync(0xFFFFFFFFu, s, 1);
                s += __shfl_xor_sync(0xFFFFFFFFu, s, 2);
                if (tig == 0) {
                    const int row = m0 + warp_m + mt * 16 + gid + half * 8;
                    atomicAdd(out + row, s);
                }
            }
        }
    } else {
#pragma unroll
        for (int mt = 0; mt < 4; mt++) {
            const int r0 = m0 + warp_m + mt * 16 + gid;
#pragma unroll
            for (int half = 0; half < 2; half++) {
                const size_t rb = (size_t)(r0 + half * 8) * D_DIM + n0 + warp_n;
#pragma unroll
                for (int nt = 0; nt < 8; nt++) {
                    float o0 = fmaxf(acc[mt][nt][half * 2 + 0] + bv[nt][0], 0.0f);
                    float o1 = fmaxf(acc[mt][nt][half * 2 + 1] + bv[nt][1], 0.0f);
                    __half2 hp = __floats2half2_rn(o0, o1);
                    *reinterpret_cast<__half2*>(C + rb + nt * 8 + tig * 2) = hp;
                }
            }
        }
    }
}

// ---------------- Merged prologue ----------------
#define PRO_W0 1024
#define PRO_SX 1024
#define PRO_SM 16
#define PRO_TOTAL (PRO_W0 + PRO_SX + PRO_SM)

__global__ void __launch_bounds__(256) prologue(
    const float4* __restrict__ wmu, const float4* __restrict__ wrho,
    const float4* __restrict__ weps,
    const float4* __restrict__ x,
    const float* __restrict__ bmu, const float* __restrict__ brho,
    const float* __restrict__ beps,
    const float* __restrict__ womu, const float* __restrict__ worho,
    const float* __restrict__ woeps,
    const float* __restrict__ bomu, const float* __restrict__ borho,
    const float* __restrict__ boeps,
    float* __restrict__ out)
{
    const int b = blockIdx.x;
    const int tid = threadIdx.x;

    if (b < PRO_W0) {
        const size_t n = (size_t)D_DIM * D_DIM / 4;
        prep_slab(wmu, wrho, weps, 0, n,
                  (size_t)b * 256 + tid, (size_t)PRO_W0 * 256);
    } else if (b < PRO_W0 + PRO_SX) {
        const size_t n = (size_t)B_DIM * D_DIM / 4;
        for (size_t i = (size_t)(b - PRO_W0) * 256 + tid; i < n;
             i += (size_t)PRO_SX * 256) {
            float4 v = x[i];
            __half h[4];
            h[0] = __float2half_rn(v.x);
            h[1] = __float2half_rn(v.y);
            h[2] = __float2half_rn(v.z);
            h[3] = __float2half_rn(v.w);
            reinterpret_cast<ulonglong1*>(g_a[0])[i].x =
                *reinterpret_cast<unsigned long long*>(h);
        }
    } else {
        const int t = (b - PRO_W0 - PRO_SX) * 256 + tid;
        const int stride = PRO_SM * 256;
        for (int i = t; i < H_LAYERS * D_DIM; i += stride)
            g_bias[i] = fmaf(beps[i], softplus_fast(brho[i]), bmu[i]);
        for (int i = t; i < D_DIM; i += stride)
            g_wo[i] = fmaf(woeps[i], softplus_fast(worho[i]), womu[i]);
        const float bo = fmaf(boeps[0], softplus_fast(borho[0]), bomu[0]);
        for (int i = t; i < B_DIM; i += stride)
            out[i] = bo;
    }
}

// ---------------- Launch ----------------
extern "C" void kernel_launch(void* const* d_in, const int* in_sizes, int n_in,
                              void* d_out, int out_size)
{
    (void)in_sizes; (void)n_in; (void)out_size;
    const float4* x = (const float4*)d_in[0];
    const float4* wmu = (const float4*)d_in[1];
    const float4* wrho = (const float4*)d_in[2];
    const float4* weps = (const float4*)d_in[9];
    float* out = (float*)d_out;

    static int smem_set = 0;
    if (!smem_set) {
        cudaFuncSetAttribute(gemm_split_relu, cudaFuncAttributeMaxDynamicSharedMemorySize,
                             SMEM_TOTAL);
        smem_set = 1;
    }

    prologue<<<PRO_TOTAL, 256>>>(
        wmu, wrho, weps, x,
        (const float*)d_in[3], (const float*)d_in[4], (const float*)d_in[10],
        (const float*)d_in[5], (const float*)d_in[6], (const float*)d_in[11],
        (const float*)d_in[7], (const float*)d_in[8], (const float*)d_in[12],
        out);

    gemm_split_relu<<<NTILES + PREP_CTAS, 128, SMEM_TOTAL>>>(
        0, 0, 1, 0, wmu, wrho, weps, 1, out);
    gemm_split_relu<<<NTILES + PREP_CTAS, 128, SMEM_TOTAL>>>(
        1, 1, 0, 0, wmu, wrho, weps, 2, out);
    gemm_split_relu<<<NTILES, 128, SMEM_TOTAL>>>(
        0, 2, 1, 1, wmu, wrho, weps, -1, out);
}

// round 17
// speedup vs baseline: 1.8303x; 1.0916x over previous
#include <cuda_runtime.h>
#include <cuda_fp16.h>
#include <cstdint>
#include <cstddef>

// ---------------- Problem dims ----------------
#define D_DIM 2048
#define B_DIM 4096
#define H_LAYERS 3

// ---------------- Device scratch ----------------
__device__ __half g_Whi[(size_t)H_LAYERS * D_DIM * D_DIM];
__device__ __half g_Wlo[(size_t)H_LAYERS * D_DIM * D_DIM];
__device__ float g_bias[H_LAYERS * D_DIM];
__device__ float g_wo[D_DIM];
__device__ __half g_a[2][(size_t)B_DIM * D_DIM];

// ---------------- helpers ----------------
__device__ __forceinline__ uint32_t smem_u32(const void* p) {
    uint32_t a;
    asm("{ .reg .u64 t; cvta.to.shared.u64 t, %1; cvt.u32.u64 %0, t; }" : "=r"(a) : "l"(p));
    return a;
}

#define CP_ASYNC16(dst, src) \
    asm volatile("cp.async.cg.shared.global [%0], [%1], 16;" :: "r"(dst), "l"(src) : "memory")
#define CP_COMMIT() asm volatile("cp.async.commit_group;" ::: "memory")
#define CP_WAIT(n)  asm volatile("cp.async.wait_group %0;" :: "n"(n) : "memory")

#define LDSM4(r0, r1, r2, r3, addr) \
    asm volatile("ldmatrix.sync.aligned.m8n8.x4.shared.b16 {%0,%1,%2,%3}, [%4];" \
                 : "=r"(r0), "=r"(r1), "=r"(r2), "=r"(r3) : "r"(addr))

__device__ __forceinline__ void mma_fp16(float& c0, float& c1, float& c2, float& c3,
                                         uint32_t a0, uint32_t a1, uint32_t a2, uint32_t a3,
                                         uint32_t b0, uint32_t b1) {
    asm volatile(
        "mma.sync.aligned.m16n8k16.row.col.f32.f16.f16.f32 "
        "{%0,%1,%2,%3}, {%4,%5,%6,%7}, {%8,%9}, {%0,%1,%2,%3};"
        : "+f"(c0), "+f"(c1), "+f"(c2), "+f"(c3)
        : "r"(a0), "r"(a1), "r"(a2), "r"(a3), "r"(b0), "r"(b1));
}

// MUFU-free e^x (poly 2^r + exponent bit trick)
__device__ __forceinline__ float fast_exp(float x) {
    float y = x * 1.4426950408889634f;
    float f = floorf(y);
    float r = y - f;
    float p = 1.53989903e-4f;
    p = fmaf(p, r, 1.33335581e-3f);
    p = fmaf(p, r, 9.61817249e-3f);
    p = fmaf(p, r, 5.55041087e-2f);
    p = fmaf(p, r, 2.40226507e-1f);
    p = fmaf(p, r, 6.93147181e-1f);
    p = fmaf(p, r, 1.0f);
    int i = (int)f;
    if (i < -126) i = -126;
    return p * __int_as_float((i + 127) << 23);
}

__device__ __forceinline__ float softplus_fast(float x) {
    float t = fast_exp(x);
    if (t < 0.25f) {
        float p = fmaf(t, -0.125f, 0.14285714285714285f);
        p = fmaf(t, p, -0.16666666666666666f);
        p = fmaf(t, p, 0.2f);
        p = fmaf(t, p, -0.25f);
        p = fmaf(t, p, 0.3333333333333333f);
        p = fmaf(t, p, -0.5f);
        p = fmaf(t, p, 1.0f);
        return t * p;
    }
    return 0.6931471805599453f * log2f(1.0f + t);
}

__device__ __forceinline__ void split_fp16(float v, __half& hi, __half& lo) {
    hi = __float2half_rn(v);
    lo = __float2half_rn(v - __half2float(hi));
}

__device__ __forceinline__ void prep_slab(const float4* __restrict__ mu,
                                          const float4* __restrict__ rho,
                                          const float4* __restrict__ eps,
                                          size_t off, size_t n,
                                          size_t start, size_t stride)
{
    for (size_t i = start; i < n; i += stride) {
        float4 m = mu[off + i], r = rho[off + i], e = eps[off + i];
        float w0 = fmaf(e.x, softplus_fast(r.x), m.x);
        float w1 = fmaf(e.y, softplus_fast(r.y), m.y);
        float w2 = fmaf(e.z, softplus_fast(r.z), m.z);
        float w3 = fmaf(e.w, softplus_fast(r.w), m.w);
        __half h[4], l[4];
        split_fp16(w0, h[0], l[0]);
        split_fp16(w1, h[1], l[1]);
        split_fp16(w2, h[2], l[2]);
        split_fp16(w3, h[3], l[3]);
        reinterpret_cast<ulonglong1*>(g_Whi)[off + i].x =
            *reinterpret_cast<unsigned long long*>(h);
        reinterpret_cast<ulonglong1*>(g_Wlo)[off + i].x =
            *reinterpret_cast<unsigned long long*>(l);
    }
}

// ---------------- GEMM config ----------------
#define BM 128
#define BN 128
#define BK 64
#define NKT (D_DIM / BK)          // 32
#define NTILES 512
#define PREP_CTAS 128
// 128B rows, SW128 swizzle: chunk' = chunk ^ (row & 7)
#define PLANE_B 16384             // 128 rows * 128B
#define STAGE_B (3 * PLANE_B)     // A, Whi, Wlo = 49152 B
#define NSTAGE 2
#define SMEM_TOTAL (NSTAGE * STAGE_B)   // 98304 B -> 2 CTAs/SM

__global__ void __launch_bounds__(128, 2)
gemm_split_relu(int a_sel, int layer, int c_sel, int fuse_out,
                const float4* __restrict__ pmu, const float4* __restrict__ prho,
                const float4* __restrict__ peps, int prep_layer,
                float* __restrict__ out)
{
    extern __shared__ __half smem[];

    const int bid = blockIdx.x;
    const int tid = threadIdx.x;

    if (bid >= NTILES) {
        const size_t slab = (size_t)D_DIM * D_DIM / 4;
        const size_t off = (size_t)prep_layer * slab;
        const size_t start = (size_t)(bid - NTILES) * 128 + tid;
        prep_slab(pmu, prho, peps, off, slab, start, (size_t)PREP_CTAS * 128);
        return;
    }

    const int wid = tid >> 5, lane = tid & 31;
    const int gid = lane >> 2, tig = lane & 3;

    const __half* A = g_a[a_sel];
    const __half* Whi = g_Whi + (size_t)layer * D_DIM * D_DIM;
    const __half* Wlo = g_Wlo + (size_t)layer * D_DIM * D_DIM;
    const float* bias = g_bias + layer * D_DIM;
    __half* C = g_a[c_sel];

    const int m0 = (bid >> 4) * BM;
    const int n0 = (bid & 15) * BN;

    // ---- loader: 128 threads = 16 rows x 8 chunks per pass, 8 passes per plane ----
    const int lrow = tid >> 3;                  // 0..15
    const int lc = tid & 7;                     // 16B chunk within 128B row
    const int pc = lc ^ (lrow & 7);             // swizzle (row&7 invariant under row+16)
    const uint32_t sbase = smem_u32(smem);
    const uint32_t dst_off = (uint32_t)(lrow * 128 + pc * 16);

    const __half* gA   = A   + (size_t)(m0 + lrow) * D_DIM + lc * 8;
    const __half* gWhi = Whi + (size_t)(n0 + lrow) * D_DIM + lc * 8;
    const __half* gWlo = Wlo + (size_t)(n0 + lrow) * D_DIM + lc * 8;

    // ---- warp tiling: 2(m) x 2(n); warp tile 64x64 ----
    const int warp_m = (wid & 1) * 64;
    const int warp_n = (wid >> 1) * 64;

    const int a_row = warp_m + ((lane >> 3) & 1) * 8 + (lane & 7);
    const uint32_t a_base = (uint32_t)(a_row * 128);
    const int a_sw = a_row & 7;
    const int a_half = lane >> 4;
    const int b_row = warp_n + (lane >> 4) * 8 + (lane & 7);
    const uint32_t b_base = (uint32_t)(b_row * 128);
    const int b_sw = b_row & 7;
    const int b_half = (lane >> 3) & 1;

    float acc[4][8][4];
#pragma unroll
    for (int i = 0; i < 4; i++)
#pragma unroll
        for (int j = 0; j < 8; j++)
#pragma unroll
            for (int r = 0; r < 4; r++) acc[i][j][r] = 0.0f;

#define LOAD_STAGE(stage_idx, kt_) do {                                              \
        const uint32_t so = sbase + (uint32_t)(stage_idx) * STAGE_B;                 \
        const size_t ko = (size_t)(kt_) * BK;                                        \
        _Pragma("unroll")                                                            \
        for (int p = 0; p < 8; p++) {                                                \
            const uint32_t d = so + dst_off + p * 2048;                              \
            const size_t g = ko + (size_t)p * 16 * D_DIM;                            \
            CP_ASYNC16(d,                gA + g);                                    \
            CP_ASYNC16(d + PLANE_B,      gWhi + g);                                  \
            CP_ASYNC16(d + 2 * PLANE_B,  gWlo + g);                                  \
        }                                                                            \
        CP_COMMIT();                                                                 \
    } while (0)

    LOAD_STAGE(0, 0);

#pragma unroll 1
    for (int kt = 0; kt < NKT; kt++) {
        CP_WAIT(0);                     // only load(kt) in flight here
        __syncthreads();                // consumers of stage kt-1 done -> safe to overwrite
        if (kt + 1 < NKT) LOAD_STAGE((kt + 1) & 1, kt + 1);

        const uint32_t st = sbase + (uint32_t)(kt & 1) * STAGE_B;
        const uint32_t sa    = st;
        const uint32_t sb_hi = st + PLANE_B;
        const uint32_t sb_lo = st + 2 * PLANE_B;

#pragma unroll
        for (int s = 0; s < 4; s++) {   // four k16 steps per 64-K tile
            const uint32_t pa = (uint32_t)((((s << 1) | a_half) ^ a_sw) * 16);
            const uint32_t pb = (uint32_t)((((s << 1) | b_half) ^ b_sw) * 16);
            uint32_t ah[4][4], bh[4][4], bl[4][4];

#pragma unroll
            for (int mt = 0; mt < 4; mt++) {
                const uint32_t ao = a_base + pa + mt * 2048;
                LDSM4(ah[mt][0], ah[mt][1], ah[mt][2], ah[mt][3], sa + ao);
            }
#pragma unroll
            for (int nt2 = 0; nt2 < 4; nt2++) {
                const uint32_t bo = b_base + pb + nt2 * 2048;
                LDSM4(bh[nt2][0], bh[nt2][1], bh[nt2][2], bh[nt2][3], sb_hi + bo);
            }

            // sweep 1: a * W_hi
#pragma unroll
            for (int mt = 0; mt < 4; mt++)
#pragma unroll
                for (int nt = 0; nt < 8; nt++) {
                    float* c = acc[mt][nt];
                    const int t2 = nt >> 1, j = (nt & 1) * 2;
                    mma_fp16(c[0], c[1], c[2], c[3],
                             ah[mt][0], ah[mt][1], ah[mt][2], ah[mt][3],
                             bh[t2][j], bh[t2][j + 1]);
                }

            // B_lo fragments late (lower live-set, spread crossbar burst)
#pragma unroll
            for (int nt2 = 0; nt2 < 4; nt2++) {
                const uint32_t bo = b_base + pb + nt2 * 2048;
                LDSM4(bl[nt2][0], bl[nt2][1], bl[nt2][2], bl[nt2][3], sb_lo + bo);
            }

            // sweep 2: a * W_lo
#pragma unroll
            for (int mt = 0; mt < 4; mt++)
#pragma unroll
                for (int nt = 0; nt < 8; nt++) {
                    float* c = acc[mt][nt];
                    const int t2 = nt >> 1, j = (nt & 1) * 2;
                    mma_fp16(c[0], c[1], c[2], c[3],
                             ah[mt][0], ah[mt][1], ah[mt][2], ah[mt][3],
                             bl[t2][j], bl[t2][j + 1]);
                }
        }
    }

    // ---- epilogue ----
    float bv[8][2];
#pragma unroll
    for (int nt = 0; nt < 8; nt++) {
        const int col = n0 + warp_n + nt * 8 + tig * 2;
        bv[nt][0] = bias[col];
        bv[nt][1] = bias[col + 1];
    }

    if (fuse_out) {
        float wv[8][2];
#pragma unroll
        for (int nt = 0; nt < 8; nt++) {
            const int col = n0 + warp_n + nt * 8 + tig * 2;
            wv[nt][0] = g_wo[col];
            wv[nt][1] = g_wo[col + 1];
        }
#pragma unroll
        for (int mt = 0; mt < 4; mt++) {
#pragma unroll
            for (int half = 0; half < 2; half++) {
                float s = 0.0f;
#pragma unroll
                for (int nt = 0; nt < 8; nt++) {
                    float o0 = fmaxf(acc[mt][nt][half * 2 + 0] + bv[nt][0], 0.0f);
                    float o1 = fmaxf(acc[mt][nt][half * 2 + 1] + bv[nt][1], 0.0f);
                    s = fmaf(o0, wv[nt][0], s);
                    s = fmaf(o1, wv[nt][1], s);
                }
                s += __shfl_xor_sync(0xFFFFFFFFu, s, 1);
                s += __shfl_xor_sync(0xFFFFFFFFu, s, 2);
                if (tig == 0) {
                    const int row = m0 + warp_m + mt * 16 + gid + half * 8;
                    atomicAdd(out + row, s);
                }
            }
        }
    } else {
#pragma unroll
        for (int mt = 0; mt < 4; mt++) {
            const int r0 = m0 + warp_m + mt * 16 + gid;
#pragma unroll
            for (int half = 0; half < 2; half++) {
                const size_t rb = (size_t)(r0 + half * 8) * D_DIM + n0 + warp_n;
#pragma unroll
                for (int nt = 0; nt < 8; nt++) {
                    float o0 = fmaxf(acc[mt][nt][half * 2 + 0] + bv[nt][0], 0.0f);
                    float o1 = fmaxf(acc[mt][nt][half * 2 + 1] + bv[nt][1], 0.0f);
                    __half2 hp = __floats2half2_rn(o0, o1);
                    *reinterpret_cast<__half2*>(C + rb + nt * 8 + tig * 2) = hp;
                }
            }
        }
    }
}

// ---------------- Merged prologue ----------------
#define PRO_W0 1024
#define PRO_SX 1024
#define PRO_SM 16
#define PRO_TOTAL (PRO_W0 + PRO_SX + PRO_SM)

__global__ void __launch_bounds__(256) prologue(
    const float4* __restrict__ wmu, const float4* __restrict__ wrho,
    const float4* __restrict__ weps,
    const float4* __restrict__ x,
    const float* __restrict__ bmu, const float* __restrict__ brho,
    const float* __restrict__ beps,
    const float* __restrict__ womu, const float* __restrict__ worho,
    const float* __restrict__ woeps,
    const float* __restrict__ bomu, const float* __restrict__ borho,
    const float* __restrict__ boeps,
    float* __restrict__ out)
{
    const int b = blockIdx.x;
    const int tid = threadIdx.x;

    if (b < PRO_W0) {
        const size_t n = (size_t)D_DIM * D_DIM / 4;
        prep_slab(wmu, wrho, weps, 0, n,
                  (size_t)b * 256 + tid, (size_t)PRO_W0 * 256);
    } else if (b < PRO_W0 + PRO_SX) {
        const size_t n = (size_t)B_DIM * D_DIM / 4;
        for (size_t i = (size_t)(b - PRO_W0) * 256 + tid; i < n;
             i += (size_t)PRO_SX * 256) {
            float4 v = x[i];
            __half h[4];
            h[0] = __float2half_rn(v.x);
            h[1] = __float2half_rn(v.y);
            h[2] = __float2half_rn(v.z);
            h[3] = __float2half_rn(v.w);
            reinterpret_cast<ulonglong1*>(g_a[0])[i].x =
                *reinterpret_cast<unsigned long long*>(h);
        }
    } else {
        const int t = (b - PRO_W0 - PRO_SX) * 256 + tid;
        const int stride = PRO_SM * 256;
        for (int i = t; i < H_LAYERS * D_DIM; i += stride)
            g_bias[i] = fmaf(beps[i], softplus_fast(brho[i]), bmu[i]);
        for (int i = t; i < D_DIM; i += stride)
            g_wo[i] = fmaf(woeps[i], softplus_fast(worho[i]), womu[i]);
        const float bo = fmaf(boeps[0], softplus_fast(borho[0]), bomu[0]);
        for (int i = t; i < B_DIM; i += stride)
            out[i] = bo;
    }
}

// ---------------- Launch ----------------
extern "C" void kernel_launch(void* const* d_in, const int* in_sizes, int n_in,
                              void* d_out, int out_size)
{
    (void)in_sizes; (void)n_in; (void)out_size;
    const float4* x = (const float4*)d_in[0];
    const float4* wmu = (const float4*)d_in[1];
    const float4* wrho = (const float4*)d_in[2];
    const float4* weps = (const float4*)d_in[9];
    float* out = (float*)d_out;

    static int smem_set = 0;
    if (!smem_set) {
        cudaFuncSetAttribute(gemm_split_relu, cudaFuncAttributeMaxDynamicSharedMemorySize,
                             SMEM_TOTAL);
        smem_set = 1;
    }

    prologue<<<PRO_TOTAL, 256>>>(
        wmu, wrho, weps, x,
        (const float*)d_in[3], (const float*)d_in[4], (const float*)d_in[10],
        (const float*)d_in[5], (const float*)d_in[6], (const float*)d_in[11],
        (const float*)d_in[7], (const float*)d_in[8], (const float*)d_in[12],
        out);

    gemm_split_relu<<<NTILES + PREP_CTAS, 128, SMEM_TOTAL>>>(
        0, 0, 1, 0, wmu, wrho, weps, 1, out);
    gemm_split_relu<<<NTILES + PREP_CTAS, 128, SMEM_TOTAL>>>(
        1, 1, 0, 0, wmu, wrho, weps, 2, out);
    gemm_split_relu<<<NTILES, 128, SMEM_TOTAL>>>(
        0, 2, 1, 1, wmu, wrho, weps, -1, out);
}